// round 1
// baseline (speedup 1.0000x reference)
#include <cuda_runtime.h>
#include <cuda_bf16.h>
#include <cstdint>

#define BB 256
#define TT 512
#define NS 256
#define START_TAG 254
#define STOP_TAG 255

// scratch (allocation-free rule: __device__ globals)
__device__ float g_den[BB];
__device__ float g_num[BB];
__device__ uint32_t g_Et[NS * 128];  // [j][pair p] packed bf16x2: lo=state 2p, hi=state 2p+1

// ---------------------------------------------------------------------------
// Prep: E[i][j] = exp(trans[i][j]) in bf16, transposed+packed for the forward kernel
// ---------------------------------------------------------------------------
__global__ void prep_kernel(const float* __restrict__ trans) {
    int idx = blockIdx.x * blockDim.x + threadIdx.x;  // 0..32767
    int j = idx >> 7;
    int p = idx & 127;
    float t0 = trans[(2 * p) * NS + j];
    float t1 = trans[(2 * p + 1) * NS + j];
    __nv_bfloat16 h0 = __float2bfloat16(__expf(t0));
    __nv_bfloat16 h1 = __float2bfloat16(__expf(t1));
    uint32_t lo = (uint32_t)__bfloat16_as_ushort(h0);
    uint32_t hi = (uint32_t)__bfloat16_as_ushort(h1);
    g_Et[j * 128 + p] = lo | (hi << 16);
}

// ---------------------------------------------------------------------------
// Forward recursion: 1 CTA = 2 batches, E resident in SMEM, 511 steps.
// Layout: 256 threads; jh = tid>>7 picks j-half; p = tid&127 picks state pair.
// Thread accumulates 4 partial dots: {state 2p, 2p+1} x {batch b0, b1}.
// ---------------------------------------------------------------------------
#define SMEM_ET    0
#define SMEM_ALPHA (131072)
#define SMEM_EA    (131072 + 2048)
#define SMEM_PART  (131072 + 4096)
#define SMEM_RED   (131072 + 8192)
#define SMEM_RSUM  (131072 + 8192 + 64)
#define SMEM_TOTAL (131072 + 8192 + 128)

__global__ void __launch_bounds__(256, 1) forward_kernel(
    const float* __restrict__ inputs,
    const float* __restrict__ trans,
    const int* __restrict__ mask)
{
    extern __shared__ char smem[];
    uint32_t* Et     = (uint32_t*)(smem + SMEM_ET);
    float2*   alpha  = (float2*)(smem + SMEM_ALPHA);   // [256] {b0,b1} per state
    float2*   ea     = (float2*)(smem + SMEM_EA);      // [256]
    float4*   part   = (float4*)(smem + SMEM_PART);    // [256]
    float2*   red    = (float2*)(smem + SMEM_RED);     // [8]
    float2*   rsum   = (float2*)(smem + SMEM_RSUM);    // [8]

    const int tid  = threadIdx.x;
    const int lane = tid & 31;
    const int wid  = tid >> 5;
    const int b0 = blockIdx.x * 2;
    const int b1 = b0 + 1;

    // stage E into shared (coalesced uint4)
    {
        const uint4* src = (const uint4*)g_Et;
        uint4* dst = (uint4*)Et;
#pragma unroll
        for (int k = 0; k < 32; k++)
            dst[tid + 256 * k] = src[tid + 256 * k];
    }

    // alpha0[b,i] = trans[i, START] + inputs[b,0,i]
    {
        float tS = trans[tid * NS + START_TAG];
        float a0 = tS + inputs[(size_t)b0 * TT * NS + tid];
        float a1 = tS + inputs[(size_t)b1 * TT * NS + tid];
        alpha[tid] = make_float2(a0, a1);
    }
    __syncthreads();

    const int p  = tid & 127;
    const int jh = tid >> 7;
    const uint32_t* Eb = Et + jh * 128 * 128 + p;
    const float2* pin0 = (const float2*)inputs + (size_t)b0 * TT * 128 + p;
    const float2* pin1 = (const float2*)inputs + (size_t)b1 * TT * 128 + p;
    const int* pm0 = mask + b0 * TT;
    const int* pm1 = mask + b1 * TT;

    for (int t = 1; t < TT; t++) {
        // prefetch emissions / mask early (hidden under the reductions + dot)
        float2 em0, em1;
        int mk0 = 1, mk1 = 1;
        if (jh == 0) {
            em0 = pin0[(size_t)t * 128];
            em1 = pin1[(size_t)t * 128];
            mk0 = pm0[t - 1];
            mk1 = pm1[t - 1];
        }

        // phase A: per-batch max of alpha
        float2 av = alpha[tid];
        float mx0 = av.x, mx1 = av.y;
#pragma unroll
        for (int o = 16; o; o >>= 1) {
            mx0 = fmaxf(mx0, __shfl_xor_sync(0xffffffffu, mx0, o));
            mx1 = fmaxf(mx1, __shfl_xor_sync(0xffffffffu, mx1, o));
        }
        if (lane == 0) red[wid] = make_float2(mx0, mx1);
        __syncthreads();
        float m0 = -INFINITY, m1 = -INFINITY;
#pragma unroll
        for (int w = 0; w < 8; w++) {
            float2 r = red[w];
            m0 = fmaxf(m0, r.x);
            m1 = fmaxf(m1, r.y);
        }

        // phase B: ea = exp(alpha - m), plus block sums (for mask==0 path)
        float e0 = __expf(av.x - m0);
        float e1 = __expf(av.y - m1);
        ea[tid] = make_float2(e0, e1);
        float s0 = e0, s1 = e1;
#pragma unroll
        for (int o = 16; o; o >>= 1) {
            s0 += __shfl_xor_sync(0xffffffffu, s0, o);
            s1 += __shfl_xor_sync(0xffffffffu, s1, o);
        }
        if (lane == 0) rsum[wid] = make_float2(s0, s1);
        __syncthreads();

        // phase C: half-range dot products (128 j per thread)
        float acc00 = 0.f, acc01 = 0.f, acc10 = 0.f, acc11 = 0.f;
        const float2* eab = ea + jh * 128;
#pragma unroll 8
        for (int jj = 0; jj < 128; jj++) {
            uint32_t v = Eb[jj * 128];
            float2 w = eab[jj];
            float f0 = __uint_as_float(v << 16);
            float f1 = __uint_as_float(v & 0xFFFF0000u);
            acc00 = fmaf(f0, w.x, acc00);
            acc01 = fmaf(f0, w.y, acc01);
            acc10 = fmaf(f1, w.x, acc10);
            acc11 = fmaf(f1, w.y, acc11);
        }
        part[tid] = make_float4(acc00, acc01, acc10, acc11);
        __syncthreads();

        // phase D: combine halves, log, add emissions, write alpha
        if (jh == 0) {
            float4 q = part[tid + 128];
            acc00 += q.x; acc01 += q.y; acc10 += q.z; acc11 += q.w;
            float n00, n01, n10, n11;
            if (mk0) {
                n00 = em0.x + m0 + __logf(acc00);
                n10 = em0.y + m0 + __logf(acc10);
            } else {
                float S0 = 0.f;
#pragma unroll
                for (int w = 0; w < 8; w++) S0 += rsum[w].x;
                float l = m0 + __logf(S0);
                n00 = l; n10 = l;
            }
            if (mk1) {
                n01 = em1.x + m1 + __logf(acc01);
                n11 = em1.y + m1 + __logf(acc11);
            } else {
                float S1 = 0.f;
#pragma unroll
                for (int w = 0; w < 8; w++) S1 += rsum[w].y;
                float l = m1 + __logf(S1);
                n01 = l; n11 = l;
            }
            ((float4*)alpha)[p] = make_float4(n00, n01, n10, n11);
        }
        __syncthreads();
    }

    // finalize: den[b] = LSE_i(alpha[b,i] + trans[STOP,i])
    {
        float2 av = alpha[tid];
        float ts = trans[STOP_TAG * NS + tid];
        float v0 = av.x + ts, v1 = av.y + ts;
        float mx0 = v0, mx1 = v1;
#pragma unroll
        for (int o = 16; o; o >>= 1) {
            mx0 = fmaxf(mx0, __shfl_xor_sync(0xffffffffu, mx0, o));
            mx1 = fmaxf(mx1, __shfl_xor_sync(0xffffffffu, mx1, o));
        }
        if (lane == 0) red[wid] = make_float2(mx0, mx1);
        __syncthreads();
        float m0 = -INFINITY, m1 = -INFINITY;
#pragma unroll
        for (int w = 0; w < 8; w++) {
            float2 r = red[w];
            m0 = fmaxf(m0, r.x);
            m1 = fmaxf(m1, r.y);
        }
        float e0 = __expf(v0 - m0), e1 = __expf(v1 - m1);
#pragma unroll
        for (int o = 16; o; o >>= 1) {
            e0 += __shfl_xor_sync(0xffffffffu, e0, o);
            e1 += __shfl_xor_sync(0xffffffffu, e1, o);
        }
        if (lane == 0) rsum[wid] = make_float2(e0, e1);
        __syncthreads();
        if (tid == 0) {
            float S0 = 0.f, S1 = 0.f;
#pragma unroll
            for (int w = 0; w < 8; w++) { S0 += rsum[w].x; S1 += rsum[w].y; }
            g_den[b0] = m0 + __logf(S0);
            g_den[b1] = m1 + __logf(S1);
        }
    }
}

// ---------------------------------------------------------------------------
// Numerator: 1 warp per batch
// ---------------------------------------------------------------------------
__global__ void num_kernel(const float* __restrict__ inputs,
                           const float* __restrict__ trans,
                           const int* __restrict__ tags,
                           const int* __restrict__ mask)
{
    int b = blockIdx.x;
    int lane = threadIdx.x;
    const int* tg = tags + b * TT;
    const int* mk = mask + b * TT;
    float sc = 0.f;
    int mc = 0;
    for (int t = lane; t < TT; t += 32) {
        int tgt = tg[t];
        int m = mk[t];
        mc += m;
        if (t >= 1) sc += trans[tgt * NS + tg[t - 1]] * (float)m;
        if (t < TT - 1) sc += inputs[((size_t)b * TT + t) * NS + tgt] * (float)m;
    }
#pragma unroll
    for (int o = 16; o; o >>= 1) {
        sc += __shfl_xor_sync(0xffffffffu, sc, o);
        mc += __shfl_xor_sync(0xffffffffu, mc, o);
    }
    if (lane == 0) {
        sc += trans[tg[0] * NS + START_TAG];
        int li = mc - 1;
        if (li < 0) li = 0;
        int lt = tg[li];
        sc += trans[STOP_TAG * NS + lt]
            + inputs[((size_t)b * TT + (TT - 1)) * NS + lt] * (float)mk[TT - 1];
        g_num[b] = sc;
    }
}

// ---------------------------------------------------------------------------
// Final reduce: sum_b (num - den)
// ---------------------------------------------------------------------------
__global__ void final_kernel(float* __restrict__ out)
{
    __shared__ float red[8];
    int tid = threadIdx.x;
    int lane = tid & 31, wid = tid >> 5;
    float v = g_num[tid] - g_den[tid];
#pragma unroll
    for (int o = 16; o; o >>= 1) v += __shfl_xor_sync(0xffffffffu, v, o);
    if (lane == 0) red[wid] = v;
    __syncthreads();
    if (tid == 0) {
        float s = 0.f;
#pragma unroll
        for (int w = 0; w < 8; w++) s += red[w];
        out[0] = s;
    }
}

extern "C" void kernel_launch(void* const* d_in, const int* in_sizes, int n_in,
                              void* d_out, int out_size)
{
    const float* inputs = (const float*)d_in[0];
    const float* trans  = (const float*)d_in[1];
    const int*   tags   = (const int*)d_in[2];
    const int*   mask   = (const int*)d_in[3];

    cudaFuncSetAttribute(forward_kernel,
                         cudaFuncAttributeMaxDynamicSharedMemorySize, SMEM_TOTAL);

    prep_kernel<<<256, 128>>>(trans);
    forward_kernel<<<BB / 2, 256, SMEM_TOTAL>>>(inputs, trans, mask);
    num_kernel<<<BB, 32>>>(inputs, trans, tags, mask);
    final_kernel<<<1, 256>>>((float*)d_out);
}

// round 2
// speedup vs baseline: 1.6158x; 1.6158x over previous
#include <cuda_runtime.h>
#include <cuda_bf16.h>
#include <cstdint>

#define BB 256
#define TT 512
#define NS 256
#define START_TAG 254
#define STOP_TAG 255

// scratch (allocation-free rule: __device__ globals)
__device__ float g_den[BB];
__device__ float g_num[BB];
// register-half of E: [jh][k][p][4] u64 packed f32x2 pairs over adjacent j
__device__ unsigned long long g_Ereg[2 * 16 * 128 * 4];   // 128 KB
// smem-half of E: [jh][k][p] uint4 of bf16x2 words            64 KB
__device__ uint4 g_Esm[2 * 16 * 128];

// ---------------------------------------------------------------------------
// helpers
// ---------------------------------------------------------------------------
__device__ __forceinline__ unsigned long long packf2(float lo, float hi) {
    return ((unsigned long long)__float_as_uint(hi) << 32) | (unsigned long long)__float_as_uint(lo);
}
__device__ __forceinline__ uint32_t bfpack(float lo, float hi) {
    uint32_t l = (uint32_t)__bfloat16_as_ushort(__float2bfloat16(lo));
    uint32_t h = (uint32_t)__bfloat16_as_ushort(__float2bfloat16(hi));
    return l | (h << 16);
}
// expand bf16x2 word -> packed f32x2 (lo lane = low bf16)
__device__ __forceinline__ unsigned long long bf2f2(uint32_t v) {
    uint32_t lo = v << 16;
    uint32_t hi = v & 0xFFFF0000u;
    return ((unsigned long long)hi << 32) | (unsigned long long)lo;
}
__device__ __forceinline__ float f2sum(unsigned long long v) {
    return __uint_as_float((uint32_t)v) + __uint_as_float((uint32_t)(v >> 32));
}

#define FMA2(d, a, b) \
    asm volatile("fma.rn.f32x2 %0, %1, %2, %0;" : "+l"(d) : "l"(a), "l"(b))
#define LDSV2(a, b, addr) \
    asm volatile("ld.shared.v2.u64 {%0,%1}, [%2];" : "=l"(a), "=l"(b) : "r"(addr))

// ---------------------------------------------------------------------------
// Prep: build both E representations. idx<4096 -> register half (f32x2 pairs),
// idx>=4096 -> smem half (bf16x2 uint4). j pairing is adjacent (2q, 2q+1).
// ---------------------------------------------------------------------------
__global__ void prep_kernel(const float* __restrict__ trans) {
    int idx = blockIdx.x * blockDim.x + threadIdx.x;  // 0..8191
    int p  = idx & 127;
    int k  = (idx >> 7) & 15;
    int jh = (idx >> 11) & 1;
    bool do_sm = idx >= 4096;
    int j0 = jh * 128 + (do_sm ? 64 : 0) + 4 * k;
    int s0 = 2 * p, s1 = 2 * p + 1;
    float e0a = __expf(trans[s0 * NS + j0 + 0]);
    float e0b = __expf(trans[s0 * NS + j0 + 1]);
    float e0c = __expf(trans[s0 * NS + j0 + 2]);
    float e0d = __expf(trans[s0 * NS + j0 + 3]);
    float e1a = __expf(trans[s1 * NS + j0 + 0]);
    float e1b = __expf(trans[s1 * NS + j0 + 1]);
    float e1c = __expf(trans[s1 * NS + j0 + 2]);
    float e1d = __expf(trans[s1 * NS + j0 + 3]);
    if (!do_sm) {
        unsigned long long* dst = g_Ereg + ((size_t)((jh * 16 + k) * 128 + p)) * 4;
        dst[0] = packf2(e0a, e0b);  // s0, q0
        dst[1] = packf2(e1a, e1b);  // s1, q0
        dst[2] = packf2(e0c, e0d);  // s0, q1
        dst[3] = packf2(e1c, e1d);  // s1, q1
    } else {
        uint4 v;
        v.x = bfpack(e0a, e0b);
        v.y = bfpack(e1a, e1b);
        v.z = bfpack(e0c, e0d);
        v.w = bfpack(e1c, e1d);
        g_Esm[(jh * 16 + k) * 128 + p] = v;
    }
}

// ---------------------------------------------------------------------------
// Forward recursion
// ---------------------------------------------------------------------------
#define SMEM_ESM   0        // 65536
#define SMEM_ALPHA 65536    // 2048  float2[256]
#define SMEM_EAJ0  67584    // 1024  float[256]
#define SMEM_EAJ1  68608    // 1024
#define SMEM_PART  69632    // 4096  float4[256]
#define SMEM_MRED  73728    // 64    float2[8]
#define SMEM_RSUM  73792    // 64    float2[8]
#define SMEM_TOTAL 73856

__global__ void __launch_bounds__(256, 1) forward_kernel(
    const float* __restrict__ inputs,
    const float* __restrict__ trans,
    const int* __restrict__ mask)
{
    extern __shared__ char smem[];
    uint4*  Esm   = (uint4*)(smem + SMEM_ESM);
    float2* alpha = (float2*)(smem + SMEM_ALPHA);
    float*  eaj0  = (float*)(smem + SMEM_EAJ0);
    float*  eaj1  = (float*)(smem + SMEM_EAJ1);
    float4* part  = (float4*)(smem + SMEM_PART);
    float2* mred  = (float2*)(smem + SMEM_MRED);
    float2* rsum  = (float2*)(smem + SMEM_RSUM);

    const int tid  = threadIdx.x;
    const int lane = tid & 31;
    const int wid  = tid >> 5;
    const int p    = tid & 127;
    const int jh   = tid >> 7;
    const int b0   = blockIdx.x * 2;
    const int b1   = b0 + 1;

    // stage smem half of E
    for (int i = tid; i < 4096; i += 256) Esm[i] = g_Esm[i];

    // load register half of E (fully unrolled -> stays in registers)
    unsigned long long Er[64];
    {
        const ulonglong2* gE = (const ulonglong2*)g_Ereg + (size_t)jh * 16 * 128 * 2;
#pragma unroll
        for (int k = 0; k < 16; k++) {
            ulonglong2 a = gE[(k * 128 + p) * 2];
            ulonglong2 b = gE[(k * 128 + p) * 2 + 1];
            Er[4 * k + 0] = a.x;
            Er[4 * k + 1] = a.y;
            Er[4 * k + 2] = b.x;
            Er[4 * k + 3] = b.y;
        }
    }

    // alpha0 + initial max -> mred[0..3]
    {
        float tS = trans[tid * NS + START_TAG];
        float a0 = tS + inputs[(size_t)b0 * TT * NS + tid];
        float a1 = tS + inputs[(size_t)b1 * TT * NS + tid];
        alpha[tid] = make_float2(a0, a1);
        float mx0 = a0, mx1 = a1;
#pragma unroll
        for (int o = 16; o; o >>= 1) {
            mx0 = fmaxf(mx0, __shfl_xor_sync(0xffffffffu, mx0, o));
            mx1 = fmaxf(mx1, __shfl_xor_sync(0xffffffffu, mx1, o));
        }
        if (lane == 0) rsum[wid] = make_float2(mx0, mx1);  // rsum as scratch
        __syncthreads();
        float m0 = -INFINITY, m1 = -INFINITY;
#pragma unroll
        for (int w = 0; w < 8; w++) {
            float2 r = rsum[w];
            m0 = fmaxf(m0, r.x);
            m1 = fmaxf(m1, r.y);
        }
        if (tid < 4) mred[tid] = make_float2(m0, m1);
        __syncthreads();
    }

    const uint32_t eaj0a = (uint32_t)__cvta_generic_to_shared(eaj0) + jh * 512;
    const uint32_t eaj1a = (uint32_t)__cvta_generic_to_shared(eaj1) + jh * 512;
    const float* in0 = inputs + (size_t)b0 * TT * NS + 2 * p;
    const float* in1 = inputs + (size_t)b1 * TT * NS + 2 * p;
    const int* pm0 = mask + b0 * TT;
    const int* pm1 = mask + b1 * TT;

    // preload emissions/mask for t=1
    float2 em0c = make_float2(0.f, 0.f), em1c = make_float2(0.f, 0.f);
    int mk0c = 1, mk1c = 1;
    if (jh == 0) {
        em0c = *(const float2*)(in0 + (size_t)1 * NS);
        em1c = *(const float2*)(in1 + (size_t)1 * NS);
        mk0c = pm0[0];
        mk1c = pm1[0];
    }

    for (int t = 1; t < TT; t++) {
        // ---- phase B: read max, exp, publish ea ----
        float2 av = alpha[tid];
        float2 r0 = mred[0], r1 = mred[1], r2 = mred[2], r3 = mred[3];
        float m0 = fmaxf(fmaxf(r0.x, r1.x), fmaxf(r2.x, r3.x));
        float m1 = fmaxf(fmaxf(r0.y, r1.y), fmaxf(r2.y, r3.y));
        float e0 = __expf(av.x - m0);
        float e1 = __expf(av.y - m1);
        eaj0[tid] = e0;
        eaj1[tid] = e1;
        if ((mk0c & mk1c) == 0) {  // rare masked path: need plain sums
            float s0 = e0, s1 = e1;
#pragma unroll
            for (int o = 16; o; o >>= 1) {
                s0 += __shfl_xor_sync(0xffffffffu, s0, o);
                s1 += __shfl_xor_sync(0xffffffffu, s1, o);
            }
            if (lane == 0) rsum[wid] = make_float2(s0, s1);
        }
        __syncthreads();

        // prefetch next-step emissions / mask (hidden under the dot)
        float2 em0n = make_float2(0.f, 0.f), em1n = make_float2(0.f, 0.f);
        int mk0n = 1, mk1n = 1;
        if (jh == 0 && t + 1 < TT) {
            em0n = *(const float2*)(in0 + (size_t)(t + 1) * NS);
            em1n = *(const float2*)(in1 + (size_t)(t + 1) * NS);
            mk0n = pm0[t];
            mk1n = pm1[t];
        }

        // ---- phase C: dot (register half then smem half) ----
        unsigned long long acc00 = 0ull, acc01 = 0ull, acc10 = 0ull, acc11 = 0ull;
#pragma unroll
        for (int k = 0; k < 16; k++) {
            unsigned long long wa0, wb0, wa1, wb1;
            LDSV2(wa0, wb0, eaj0a + 16 * k);
            LDSV2(wa1, wb1, eaj1a + 16 * k);
            FMA2(acc00, Er[4 * k + 0], wa0);
            FMA2(acc01, Er[4 * k + 0], wa1);
            FMA2(acc10, Er[4 * k + 1], wa0);
            FMA2(acc11, Er[4 * k + 1], wa1);
            FMA2(acc00, Er[4 * k + 2], wb0);
            FMA2(acc01, Er[4 * k + 2], wb1);
            FMA2(acc10, Er[4 * k + 3], wb0);
            FMA2(acc11, Er[4 * k + 3], wb1);
        }
        {
            const uint4* Eb = Esm + jh * 2048 + p;
#pragma unroll
            for (int k = 0; k < 16; k++) {
                uint4 ev = Eb[k * 128];
                unsigned long long e0q0 = bf2f2(ev.x);
                unsigned long long e1q0 = bf2f2(ev.y);
                unsigned long long e0q1 = bf2f2(ev.z);
                unsigned long long e1q1 = bf2f2(ev.w);
                unsigned long long wa0, wb0, wa1, wb1;
                LDSV2(wa0, wb0, eaj0a + 256 + 16 * k);
                LDSV2(wa1, wb1, eaj1a + 256 + 16 * k);
                FMA2(acc00, e0q0, wa0);
                FMA2(acc01, e0q0, wa1);
                FMA2(acc10, e1q0, wa0);
                FMA2(acc11, e1q0, wa1);
                FMA2(acc00, e0q1, wb0);
                FMA2(acc01, e0q1, wb1);
                FMA2(acc10, e1q1, wb0);
                FMA2(acc11, e1q1, wb1);
            }
        }
        if (jh) {
            part[tid] = make_float4(f2sum(acc00), f2sum(acc01), f2sum(acc10), f2sum(acc11));
        }
        __syncthreads();

        // ---- phase D: combine halves, log, emissions, new alpha + new max ----
        if (jh == 0) {
            float4 q = part[tid + 128];
            float s00 = f2sum(acc00) + q.x;
            float s01 = f2sum(acc01) + q.y;
            float s10 = f2sum(acc10) + q.z;
            float s11 = f2sum(acc11) + q.w;
            float n00, n01, n10, n11;
            if (mk0c) {
                n00 = em0c.x + m0 + __logf(s00);
                n10 = em0c.y + m0 + __logf(s10);
            } else {
                float S0 = 0.f;
#pragma unroll
                for (int w = 0; w < 8; w++) S0 += rsum[w].x;
                float l = m0 + __logf(S0);
                n00 = l; n10 = l;
            }
            if (mk1c) {
                n01 = em1c.x + m1 + __logf(s01);
                n11 = em1c.y + m1 + __logf(s11);
            } else {
                float S1 = 0.f;
#pragma unroll
                for (int w = 0; w < 8; w++) S1 += rsum[w].y;
                float l = m1 + __logf(S1);
                n01 = l; n11 = l;
            }
            ((float4*)alpha)[p] = make_float4(n00, n01, n10, n11);
            // per-batch max of the new alpha (4 warps cover all 256 states)
            float lm0 = fmaxf(n00, n10);
            float lm1 = fmaxf(n01, n11);
#pragma unroll
            for (int o = 16; o; o >>= 1) {
                lm0 = fmaxf(lm0, __shfl_xor_sync(0xffffffffu, lm0, o));
                lm1 = fmaxf(lm1, __shfl_xor_sync(0xffffffffu, lm1, o));
            }
            if (lane == 0) mred[wid] = make_float2(lm0, lm1);
        }
        em0c = em0n; em1c = em1n; mk0c = mk0n; mk1c = mk1n;
        __syncthreads();
    }

    // finalize: den[b] = LSE_i(alpha[b,i] + trans[STOP,i])
    {
        float2 av = alpha[tid];
        float ts = trans[STOP_TAG * NS + tid];
        float v0 = av.x + ts, v1 = av.y + ts;
        float mx0 = v0, mx1 = v1;
#pragma unroll
        for (int o = 16; o; o >>= 1) {
            mx0 = fmaxf(mx0, __shfl_xor_sync(0xffffffffu, mx0, o));
            mx1 = fmaxf(mx1, __shfl_xor_sync(0xffffffffu, mx1, o));
        }
        if (lane == 0) mred[wid] = make_float2(mx0, mx1);
        __syncthreads();
        float m0 = -INFINITY, m1 = -INFINITY;
#pragma unroll
        for (int w = 0; w < 8; w++) {
            float2 r = mred[w];
            m0 = fmaxf(m0, r.x);
            m1 = fmaxf(m1, r.y);
        }
        float e0 = __expf(v0 - m0), e1 = __expf(v1 - m1);
#pragma unroll
        for (int o = 16; o; o >>= 1) {
            e0 += __shfl_xor_sync(0xffffffffu, e0, o);
            e1 += __shfl_xor_sync(0xffffffffu, e1, o);
        }
        if (lane == 0) rsum[wid] = make_float2(e0, e1);
        __syncthreads();
        if (tid == 0) {
            float S0 = 0.f, S1 = 0.f;
#pragma unroll
            for (int w = 0; w < 8; w++) { S0 += rsum[w].x; S1 += rsum[w].y; }
            g_den[b0] = m0 + __logf(S0);
            g_den[b1] = m1 + __logf(S1);
        }
    }
}

// ---------------------------------------------------------------------------
// Numerator: 1 warp per batch
// ---------------------------------------------------------------------------
__global__ void num_kernel(const float* __restrict__ inputs,
                           const float* __restrict__ trans,
                           const int* __restrict__ tags,
                           const int* __restrict__ mask)
{
    int b = blockIdx.x;
    int lane = threadIdx.x;
    const int* tg = tags + b * TT;
    const int* mk = mask + b * TT;
    float sc = 0.f;
    int mc = 0;
    for (int t = lane; t < TT; t += 32) {
        int tgt = tg[t];
        int m = mk[t];
        mc += m;
        if (t >= 1) sc += trans[tgt * NS + tg[t - 1]] * (float)m;
        if (t < TT - 1) sc += inputs[((size_t)b * TT + t) * NS + tgt] * (float)m;
    }
#pragma unroll
    for (int o = 16; o; o >>= 1) {
        sc += __shfl_xor_sync(0xffffffffu, sc, o);
        mc += __shfl_xor_sync(0xffffffffu, mc, o);
    }
    if (lane == 0) {
        sc += trans[tg[0] * NS + START_TAG];
        int li = mc - 1;
        if (li < 0) li = 0;
        int lt = tg[li];
        sc += trans[STOP_TAG * NS + lt]
            + inputs[((size_t)b * TT + (TT - 1)) * NS + lt] * (float)mk[TT - 1];
        g_num[b] = sc;
    }
}

// ---------------------------------------------------------------------------
// Final reduce: sum_b (num - den)
// ---------------------------------------------------------------------------
__global__ void final_kernel(float* __restrict__ out)
{
    __shared__ float red[8];
    int tid = threadIdx.x;
    int lane = tid & 31, wid = tid >> 5;
    float v = g_num[tid] - g_den[tid];
#pragma unroll
    for (int o = 16; o; o >>= 1) v += __shfl_xor_sync(0xffffffffu, v, o);
    if (lane == 0) red[wid] = v;
    __syncthreads();
    if (tid == 0) {
        float s = 0.f;
#pragma unroll
        for (int w = 0; w < 8; w++) s += red[w];
        out[0] = s;
    }
}

extern "C" void kernel_launch(void* const* d_in, const int* in_sizes, int n_in,
                              void* d_out, int out_size)
{
    const float* inputs = (const float*)d_in[0];
    const float* trans  = (const float*)d_in[1];
    const int*   tags   = (const int*)d_in[2];
    const int*   mask   = (const int*)d_in[3];

    cudaFuncSetAttribute(forward_kernel,
                         cudaFuncAttributeMaxDynamicSharedMemorySize, SMEM_TOTAL);

    prep_kernel<<<64, 128>>>(trans);
    forward_kernel<<<BB / 2, 256, SMEM_TOTAL>>>(inputs, trans, mask);
    num_kernel<<<BB, 32>>>(inputs, trans, tags, mask);
    final_kernel<<<1, 256>>>((float*)d_out);
}

// round 3
// speedup vs baseline: 1.7498x; 1.0829x over previous
#include <cuda_runtime.h>
#include <cuda_bf16.h>
#include <cstdint>

#define BB 256
#define TT 512
#define NS 256
#define START_TAG 254
#define STOP_TAG 255
#define LN2F 0.6931471805599453f

// scratch (allocation-free rule: __device__ globals)
__device__ float g_den[BB];
__device__ float g_num[BB];
// register-half of E: [jh][k][p][4] u64 packed f32x2 pairs over adjacent j
__device__ unsigned long long g_Ereg[2 * 16 * 128 * 4];   // 128 KB
// smem-half of E: [jh][k][p] uint4 of bf16x2 words            64 KB
__device__ uint4 g_Esm[2 * 16 * 128];

// ---------------------------------------------------------------------------
// helpers
// ---------------------------------------------------------------------------
__device__ __forceinline__ unsigned long long packf2(float lo, float hi) {
    return ((unsigned long long)__float_as_uint(hi) << 32) | (unsigned long long)__float_as_uint(lo);
}
__device__ __forceinline__ uint32_t bfpack(float lo, float hi) {
    uint32_t l = (uint32_t)__bfloat16_as_ushort(__float2bfloat16(lo));
    uint32_t h = (uint32_t)__bfloat16_as_ushort(__float2bfloat16(hi));
    return l | (h << 16);
}
__device__ __forceinline__ unsigned long long bf2f2(uint32_t v) {
    uint32_t lo = v << 16;
    uint32_t hi = v & 0xFFFF0000u;
    return ((unsigned long long)hi << 32) | (unsigned long long)lo;
}
__device__ __forceinline__ float f2sum(unsigned long long v) {
    return __uint_as_float((uint32_t)v) + __uint_as_float((uint32_t)(v >> 32));
}

#define FMA2(d, a, b) \
    asm volatile("fma.rn.f32x2 %0, %1, %2, %0;" : "+l"(d) : "l"(a), "l"(b))
#define ADD2(d, a) \
    asm volatile("add.rn.f32x2 %0, %0, %1;" : "+l"(d) : "l"(a))
#define LDSV2(a, b, addr) \
    asm volatile("ld.shared.v2.u64 {%0,%1}, [%2];" : "=l"(a), "=l"(b) : "r"(addr))
#define STSV2(addr, a, b) \
    asm volatile("st.shared.v2.u64 [%0], {%1,%2};" :: "r"(addr), "l"(a), "l"(b))

// ---------------------------------------------------------------------------
// Prep: E = exp(trans) in two layouts (register f32x2 half + smem bf16 half)
// ---------------------------------------------------------------------------
__global__ void prep_kernel(const float* __restrict__ trans) {
    int idx = blockIdx.x * blockDim.x + threadIdx.x;  // 0..8191
    int p  = idx & 127;
    int k  = (idx >> 7) & 15;
    int jh = (idx >> 11) & 1;
    bool do_sm = idx >= 4096;
    int j0 = jh * 128 + (do_sm ? 64 : 0) + 4 * k;
    int s0 = 2 * p, s1 = 2 * p + 1;
    float e0a = __expf(trans[s0 * NS + j0 + 0]);
    float e0b = __expf(trans[s0 * NS + j0 + 1]);
    float e0c = __expf(trans[s0 * NS + j0 + 2]);
    float e0d = __expf(trans[s0 * NS + j0 + 3]);
    float e1a = __expf(trans[s1 * NS + j0 + 0]);
    float e1b = __expf(trans[s1 * NS + j0 + 1]);
    float e1c = __expf(trans[s1 * NS + j0 + 2]);
    float e1d = __expf(trans[s1 * NS + j0 + 3]);
    if (!do_sm) {
        unsigned long long* dst = g_Ereg + ((size_t)((jh * 16 + k) * 128 + p)) * 4;
        dst[0] = packf2(e0a, e0b);
        dst[1] = packf2(e1a, e1b);
        dst[2] = packf2(e0c, e0d);
        dst[3] = packf2(e1c, e1d);
    } else {
        uint4 v;
        v.x = bfpack(e0a, e0b);
        v.y = bfpack(e1a, e1b);
        v.z = bfpack(e0c, e0d);
        v.w = bfpack(e1c, e1d);
        g_Esm[(jh * 16 + k) * 128 + p] = v;
    }
}

// ---------------------------------------------------------------------------
// Forward recursion, linear space with power-of-2 renormalization.
// ea holds v_t (scaled exp(alpha)).  alpha = log(v) + m0 + ksum*ln2.
// ---------------------------------------------------------------------------
#define SMEM_ESM   0        // 65536
#define SMEM_EAJ0  65536    // 1024  float[256]  (batch b0)
#define SMEM_EAJ1  66560    // 1024  float[256]  (batch b1)
#define SMEM_PART  67584    // 8192  32B per thread-pair slot
#define SMEM_MREDF 75776    // 8     float2 {M0,M1}
#define SMEM_SSUMF 75784    // 8     float2 {S0,S1}
#define SMEM_RED   75792    // 64    float2[8] scratch
#define SMEM_TOTAL 75856

__global__ void __launch_bounds__(256, 1) forward_kernel(
    const float* __restrict__ inputs,
    const float* __restrict__ trans,
    const int* __restrict__ mask)
{
    extern __shared__ char smem[];
    uint4*  Esm   = (uint4*)(smem + SMEM_ESM);
    float*  eaj0  = (float*)(smem + SMEM_EAJ0);
    float*  eaj1  = (float*)(smem + SMEM_EAJ1);
    float2* mredF = (float2*)(smem + SMEM_MREDF);
    float2* ssumF = (float2*)(smem + SMEM_SSUMF);
    float2* red   = (float2*)(smem + SMEM_RED);

    const int tid  = threadIdx.x;
    const int lane = tid & 31;
    const int wid  = tid >> 5;
    const int p    = tid & 127;
    const int jh   = tid >> 7;
    const int b0   = blockIdx.x * 2;
    const int b1   = b0 + 1;

    // stage smem half of E
    for (int i = tid; i < 4096; i += 256) Esm[i] = g_Esm[i];

    // load register half of E
    unsigned long long Er[64];
    {
        const ulonglong2* gE = (const ulonglong2*)g_Ereg + (size_t)jh * 16 * 128 * 2;
#pragma unroll
        for (int k = 0; k < 16; k++) {
            ulonglong2 a = gE[(k * 128 + p) * 2];
            ulonglong2 b = gE[(k * 128 + p) * 2 + 1];
            Er[4 * k + 0] = a.x;
            Er[4 * k + 1] = a.y;
            Er[4 * k + 2] = b.x;
            Er[4 * k + 3] = b.y;
        }
    }

    // alpha0, global max per batch, ea_0 = exp(alpha0 - m0)
    float C0base0, C0base1;
    {
        float tS = trans[tid * NS + START_TAG];
        float a0 = tS + inputs[(size_t)b0 * TT * NS + tid];
        float a1 = tS + inputs[(size_t)b1 * TT * NS + tid];
        float mx0 = a0, mx1 = a1;
#pragma unroll
        for (int o = 16; o; o >>= 1) {
            mx0 = fmaxf(mx0, __shfl_xor_sync(0xffffffffu, mx0, o));
            mx1 = fmaxf(mx1, __shfl_xor_sync(0xffffffffu, mx1, o));
        }
        if (lane == 0) red[wid] = make_float2(mx0, mx1);
        __syncthreads();
        float m0 = -INFINITY, m1 = -INFINITY;
#pragma unroll
        for (int w = 0; w < 8; w++) {
            float2 r = red[w];
            m0 = fmaxf(m0, r.x);
            m1 = fmaxf(m1, r.y);
        }
        C0base0 = m0;
        C0base1 = m1;
        eaj0[tid] = __expf(a0 - m0);
        eaj1[tid] = __expf(a1 - m1);
        __syncthreads();
    }

    const uint32_t eaj0a = (uint32_t)__cvta_generic_to_shared(eaj0) + jh * 512;
    const uint32_t eaj1a = (uint32_t)__cvta_generic_to_shared(eaj1) + jh * 512;
    const uint32_t partA = (uint32_t)__cvta_generic_to_shared(smem + SMEM_PART) + p * 32;
    const float* in0 = inputs + (size_t)b0 * TT * NS + 2 * p;
    const float* in1 = inputs + (size_t)b1 * TT * NS + 2 * p;
    const int* pm0 = mask + b0 * TT;
    const int* pm1 = mask + b1 * TT;

    int ksum0 = 0, ksum1 = 0;

    // preload emissions/mask for t=1
    float2 em0c = make_float2(0.f, 0.f), em1c = make_float2(0.f, 0.f);
    int mk0c = 1, mk1c = 1;
    if (jh == 0) {
        em0c = *(const float2*)(in0 + (size_t)1 * NS);
        em1c = *(const float2*)(in1 + (size_t)1 * NS);
        mk0c = pm0[0];
        mk1c = pm1[0];
    }

    for (int t = 1; t < TT; t++) {
        // es for this step (emissions prefetched a full step ago -> no stall)
        float es00, es10, es01, es11;
        if (jh == 0) {
            es00 = __expf(em0c.x);
            es10 = __expf(em0c.y);
            es01 = __expf(em1c.x);
            es11 = __expf(em1c.y);
        }

        // warp 7: per-batch max + sum of current ea (off critical path)
        if (wid == 7) {
            const float4* a0p = (const float4*)eaj0;
            const float4* a1p = (const float4*)eaj1;
            float4 x0 = a0p[lane], x1 = a0p[lane + 32];
            float4 y0 = a1p[lane], y1 = a1p[lane + 32];
            float mx0 = fmaxf(fmaxf(fmaxf(x0.x, x0.y), fmaxf(x0.z, x0.w)),
                              fmaxf(fmaxf(x1.x, x1.y), fmaxf(x1.z, x1.w)));
            float mx1 = fmaxf(fmaxf(fmaxf(y0.x, y0.y), fmaxf(y0.z, y0.w)),
                              fmaxf(fmaxf(y1.x, y1.y), fmaxf(y1.z, y1.w)));
            float s0 = (x0.x + x0.y) + (x0.z + x0.w) + (x1.x + x1.y) + (x1.z + x1.w);
            float s1 = (y0.x + y0.y) + (y0.z + y0.w) + (y1.x + y1.y) + (y1.z + y1.w);
#pragma unroll
            for (int o = 16; o; o >>= 1) {
                mx0 = fmaxf(mx0, __shfl_xor_sync(0xffffffffu, mx0, o));
                mx1 = fmaxf(mx1, __shfl_xor_sync(0xffffffffu, mx1, o));
                s0 += __shfl_xor_sync(0xffffffffu, s0, o);
                s1 += __shfl_xor_sync(0xffffffffu, s1, o);
            }
            if (lane == 0) {
                mredF[0] = make_float2(mx0, mx1);
                ssumF[0] = make_float2(s0, s1);
            }
        }

        // prefetch next-step emissions / mask
        float2 em0n = make_float2(0.f, 0.f), em1n = make_float2(0.f, 0.f);
        int mk0n = 1, mk1n = 1;
        if (jh == 0 && t + 1 < TT) {
            em0n = *(const float2*)(in0 + (size_t)(t + 1) * NS);
            em1n = *(const float2*)(in1 + (size_t)(t + 1) * NS);
            mk0n = pm0[t];
            mk1n = pm1[t];
        }

        // ---- dot: register half then smem half ----
        unsigned long long acc00 = 0ull, acc01 = 0ull, acc10 = 0ull, acc11 = 0ull;
#pragma unroll
        for (int k = 0; k < 16; k++) {
            unsigned long long wa0, wb0, wa1, wb1;
            LDSV2(wa0, wb0, eaj0a + 16 * k);
            LDSV2(wa1, wb1, eaj1a + 16 * k);
            FMA2(acc00, Er[4 * k + 0], wa0);
            FMA2(acc01, Er[4 * k + 0], wa1);
            FMA2(acc10, Er[4 * k + 1], wa0);
            FMA2(acc11, Er[4 * k + 1], wa1);
            FMA2(acc00, Er[4 * k + 2], wb0);
            FMA2(acc01, Er[4 * k + 2], wb1);
            FMA2(acc10, Er[4 * k + 3], wb0);
            FMA2(acc11, Er[4 * k + 3], wb1);
        }
        {
            const uint4* Eb = Esm + jh * 2048 + p;
#pragma unroll
            for (int k = 0; k < 16; k++) {
                uint4 ev = Eb[k * 128];
                unsigned long long e0q0 = bf2f2(ev.x);
                unsigned long long e1q0 = bf2f2(ev.y);
                unsigned long long e0q1 = bf2f2(ev.z);
                unsigned long long e1q1 = bf2f2(ev.w);
                unsigned long long wa0, wb0, wa1, wb1;
                LDSV2(wa0, wb0, eaj0a + 256 + 16 * k);
                LDSV2(wa1, wb1, eaj1a + 256 + 16 * k);
                FMA2(acc00, e0q0, wa0);
                FMA2(acc01, e0q0, wa1);
                FMA2(acc10, e1q0, wa0);
                FMA2(acc11, e1q0, wa1);
                FMA2(acc00, e0q1, wb0);
                FMA2(acc01, e0q1, wb1);
                FMA2(acc10, e1q1, wb0);
                FMA2(acc11, e1q1, wb1);
            }
        }
        if (jh) {
            STSV2(partA, acc00, acc01);
            STSV2(partA + 16, acc10, acc11);
        }
        __syncthreads();

        // ---- combine + renormalize + emission multiply (128 threads) ----
        if (jh == 0) {
            float2 MM = mredF[0];
            uint32_t e0b = __float_as_uint(MM.x) >> 23;
            uint32_t e1b = __float_as_uint(MM.y) >> 23;
            ksum0 += (int)e0b - 127;
            ksum1 += (int)e1b - 127;
            float invM0 = __uint_as_float((254u - e0b) << 23);
            float invM1 = __uint_as_float((254u - e1b) << 23);

            unsigned long long qa, qb, qc, qd;
            LDSV2(qa, qb, partA);
            LDSV2(qc, qd, partA + 16);
            ADD2(acc00, qa);
            ADD2(acc01, qb);
            ADD2(acc10, qc);
            ADD2(acc11, qd);
            float s00 = f2sum(acc00);
            float s01 = f2sum(acc01);
            float s10 = f2sum(acc10);
            float s11 = f2sum(acc11);

            float u00, u10, u01, u11;
            if (mk0c) {
                u00 = s00 * es00 * invM0;
                u10 = s10 * es10 * invM0;
            } else {
                float S0 = ssumF[0].x * invM0;
                u00 = S0; u10 = S0;
            }
            if (mk1c) {
                u01 = s01 * es01 * invM1;
                u11 = s11 * es11 * invM1;
            } else {
                float S1 = ssumF[0].y * invM1;
                u01 = S1; u11 = S1;
            }
            ((float2*)eaj0)[p] = make_float2(u00, u10);
            ((float2*)eaj1)[p] = make_float2(u01, u11);
        }
        em0c = em0n; em1c = em1n; mk0c = mk0n; mk1c = mk1n;
        __syncthreads();
    }

    // finalize: den[b] = C + log(sum_i ea[i] * exp(tstop_i))
    {
        float ets = __expf(trans[STOP_TAG * NS + tid]);
        float v0 = eaj0[tid] * ets;
        float v1 = eaj1[tid] * ets;
#pragma unroll
        for (int o = 16; o; o >>= 1) {
            v0 += __shfl_xor_sync(0xffffffffu, v0, o);
            v1 += __shfl_xor_sync(0xffffffffu, v1, o);
        }
        if (lane == 0) red[wid] = make_float2(v0, v1);
        __syncthreads();
        if (tid == 0) {
            float S0 = 0.f, S1 = 0.f;
#pragma unroll
            for (int w = 0; w < 8; w++) { S0 += red[w].x; S1 += red[w].y; }
            g_den[b0] = C0base0 + (float)ksum0 * LN2F + __logf(S0);
            g_den[b1] = C0base1 + (float)ksum1 * LN2F + __logf(S1);
        }
    }
}

// ---------------------------------------------------------------------------
// Numerator: 1 warp per batch
// ---------------------------------------------------------------------------
__global__ void num_kernel(const float* __restrict__ inputs,
                           const float* __restrict__ trans,
                           const int* __restrict__ tags,
                           const int* __restrict__ mask)
{
    int b = blockIdx.x;
    int lane = threadIdx.x;
    const int* tg = tags + b * TT;
    const int* mk = mask + b * TT;
    float sc = 0.f;
    int mc = 0;
    for (int t = lane; t < TT; t += 32) {
        int tgt = tg[t];
        int m = mk[t];
        mc += m;
        if (t >= 1) sc += trans[tgt * NS + tg[t - 1]] * (float)m;
        if (t < TT - 1) sc += inputs[((size_t)b * TT + t) * NS + tgt] * (float)m;
    }
#pragma unroll
    for (int o = 16; o; o >>= 1) {
        sc += __shfl_xor_sync(0xffffffffu, sc, o);
        mc += __shfl_xor_sync(0xffffffffu, mc, o);
    }
    if (lane == 0) {
        sc += trans[tg[0] * NS + START_TAG];
        int li = mc - 1;
        if (li < 0) li = 0;
        int lt = tg[li];
        sc += trans[STOP_TAG * NS + lt]
            + inputs[((size_t)b * TT + (TT - 1)) * NS + lt] * (float)mk[TT - 1];
        g_num[b] = sc;
    }
}

// ---------------------------------------------------------------------------
// Final reduce: sum_b (num - den)
// ---------------------------------------------------------------------------
__global__ void final_kernel(float* __restrict__ out)
{
    __shared__ float red[8];
    int tid = threadIdx.x;
    int lane = tid & 31, wid = tid >> 5;
    float v = g_num[tid] - g_den[tid];
#pragma unroll
    for (int o = 16; o; o >>= 1) v += __shfl_xor_sync(0xffffffffu, v, o);
    if (lane == 0) red[wid] = v;
    __syncthreads();
    if (tid == 0) {
        float s = 0.f;
#pragma unroll
        for (int w = 0; w < 8; w++) s += red[w];
        out[0] = s;
    }
}

extern "C" void kernel_launch(void* const* d_in, const int* in_sizes, int n_in,
                              void* d_out, int out_size)
{
    const float* inputs = (const float*)d_in[0];
    const float* trans  = (const float*)d_in[1];
    const int*   tags   = (const int*)d_in[2];
    const int*   mask   = (const int*)d_in[3];

    cudaFuncSetAttribute(forward_kernel,
                         cudaFuncAttributeMaxDynamicSharedMemorySize, SMEM_TOTAL);

    prep_kernel<<<64, 128>>>(trans);
    forward_kernel<<<BB / 2, 256, SMEM_TOTAL>>>(inputs, trans, mask);
    num_kernel<<<BB, 32>>>(inputs, trans, tags, mask);
    final_kernel<<<1, 256>>>((float*)d_out);
}

// round 5
// speedup vs baseline: 1.7564x; 1.0038x over previous
#include <cuda_runtime.h>
#include <cuda_bf16.h>
#include <cstdint>

#define BB 256
#define TT 512
#define NS 256
#define START_TAG 254
#define STOP_TAG 255
#define LN2F 0.6931471805599453f

// scratch (allocation-free rule: __device__ globals)
__device__ float g_den[BB];
__device__ float g_num[BB];
// E = exp(trans), three layouts (same for every CTA):
__device__ unsigned long long g_Er[64 * 256];  // f32x2 j-pairs, 128 KB (64 j per thread)
__device__ uint32_t g_Ebr[32 * 256];           // bf16x2 j-pairs, 32 KB (32 j per thread)
__device__ uint4 g_Esm[8 * 256];               // bf16x2 quads, 32 KB  (32 j per thread)

// ---------------------------------------------------------------------------
// helpers
// ---------------------------------------------------------------------------
__device__ __forceinline__ unsigned long long bf2f2(uint32_t v) {
    uint32_t lo = v << 16;
    uint32_t hi = v & 0xFFFF0000u;
    return ((unsigned long long)hi << 32) | (unsigned long long)lo;
}
__device__ __forceinline__ float f2sum(unsigned long long v) {
    return __uint_as_float((uint32_t)v) + __uint_as_float((uint32_t)(v >> 32));
}

#define FMA2(d, a, b) \
    asm volatile("fma.rn.f32x2 %0, %1, %2, %0;" : "+l"(d) : "l"(a), "l"(b))
#define ADD2(d, a) \
    asm volatile("add.rn.f32x2 %0, %0, %1;" : "+l"(d) : "l"(a))
#define LDSV2(a, b, addr) \
    asm volatile("ld.shared.v2.u64 {%0,%1}, [%2];" : "=l"(a), "=l"(b) : "r"(addr))
#define STSV2(addr, a, b) \
    asm volatile("st.shared.v2.u64 [%0], {%1,%2};" :: "r"(addr), "l"(a), "l"(b))

// ---------------------------------------------------------------------------
// Prep: scatter exp(trans[s][j]) into the three E layouts.
// Thread owner (p = s>>1, jh = j>>7, tidq = jh*128+p); jr = j & 127.
//   jr <  64 : f32 pair  -> g_Er  entry e = 4*(jr>>2) + 2*((jr>>1)&1) + (s&1)
//   jr <  96 : bf16 pair -> g_Ebr (local = jr-64, same e formula)
//   else     : bf16 quad -> g_Esm (local = jr-96, k = local>>2, word = 2*((local>>1)&1)+(s&1))
// ---------------------------------------------------------------------------
__global__ void prep_kernel(const float* __restrict__ trans) {
    int gid = blockIdx.x * blockDim.x + threadIdx.x;  // 0..65535
    int s = gid >> 8;
    int j = gid & 255;
    float v = __expf(trans[s * NS + j]);
    int p = s >> 1, rs = s & 1;
    int jh = j >> 7, jr = j & 127;
    int tidq = jh * 128 + p;
    if (jr < 64) {
        int e = 4 * (jr >> 2) + 2 * ((jr >> 1) & 1) + rs;
        ((float*)g_Er)[(e * 256 + tidq) * 2 + (jr & 1)] = v;
    } else if (jr < 96) {
        int local = jr - 64;
        int e = 4 * (local >> 2) + 2 * ((local >> 1) & 1) + rs;
        ((unsigned short*)g_Ebr)[(e * 256 + tidq) * 2 + (local & 1)] =
            __bfloat16_as_ushort(__float2bfloat16(v));
    } else {
        int local = jr - 96;
        int k = local >> 2;
        int w = 2 * ((local >> 1) & 1) + rs;
        ((unsigned short*)g_Esm)[((k * 256 + tidq) * 4 + w) * 2 + (local & 1)] =
            __bfloat16_as_ushort(__float2bfloat16(v));
    }
}

// ---------------------------------------------------------------------------
// Forward recursion: linear space, stale state-0 power-of-2 renorm.
// 1 CTA = 2 batches, 256 threads: p = tid&127 -> states {2p,2p+1}, jh = tid>>7
// -> j-range [jh*128, jh*128+128). Double-buffered ea.
// ---------------------------------------------------------------------------
#define SM_ESM   0        // 32768
#define SM_EA0   32768    // 2048 (2 bufs x 256 floats, batch b0)
#define SM_EA1   34816    // 2048 (batch b1)
#define SM_PART  36864    // 4096 (128 x 32B)
#define SM_MASK  40960    // 2048 (uint per t)
#define SM_MSLOT 43008    // 16   (float2[2])
#define SM_RED   43024    // 64   (float2[8])
#define SM_TOTAL 43136

__global__ void __launch_bounds__(256, 1) forward_kernel(
    const float* __restrict__ inputs,
    const float* __restrict__ trans,
    const int* __restrict__ mask)
{
    extern __shared__ char smem[];
    uint32_t smem_base = (uint32_t)__cvta_generic_to_shared(smem);
    uint4*    EsmS   = (uint4*)(smem + SM_ESM);
    uint32_t* masksS = (uint32_t*)(smem + SM_MASK);
    float2*   mslotF = (float2*)(smem + SM_MSLOT);
    float2*   redF   = (float2*)(smem + SM_RED);

    const int tid  = threadIdx.x;
    const int lane = tid & 31;
    const int wid  = tid >> 5;
    const int p    = tid & 127;
    const int jh   = tid >> 7;
    const int b0   = blockIdx.x * 2;
    const int b1   = b0 + 1;

    // stage E
    unsigned long long Er[64];
#pragma unroll
    for (int e = 0; e < 64; e++) Er[e] = g_Er[e * 256 + tid];
    uint32_t Ebr[32];
#pragma unroll
    for (int e = 0; e < 32; e++) Ebr[e] = g_Ebr[e * 256 + tid];
#pragma unroll
    for (int i = 0; i < 8; i++) EsmS[i * 256 + tid] = g_Esm[i * 256 + tid];

    // mask bitfields
    for (int tt = tid; tt < TT; tt += 256) {
        uint32_t w = (mask[b0 * TT + tt] ? 1u : 0u) | (mask[b1 * TT + tt] ? 2u : 0u);
        masksS[tt] = w;
    }

    // alpha0, global max per batch -> C0; ea_0 = exp(alpha0 - C0)
    float C00, C01;
    {
        float tS = trans[tid * NS + START_TAG];
        float a0 = tS + inputs[(size_t)b0 * TT * NS + tid];
        float a1 = tS + inputs[(size_t)b1 * TT * NS + tid];
        float mx0 = a0, mx1 = a1;
#pragma unroll
        for (int o = 16; o; o >>= 1) {
            mx0 = fmaxf(mx0, __shfl_xor_sync(0xffffffffu, mx0, o));
            mx1 = fmaxf(mx1, __shfl_xor_sync(0xffffffffu, mx1, o));
        }
        if (lane == 0) redF[wid] = make_float2(mx0, mx1);
        __syncthreads();
        float m0 = -INFINITY, m1 = -INFINITY;
#pragma unroll
        for (int w = 0; w < 8; w++) {
            float2 r = redF[w];
            m0 = fmaxf(m0, r.x);
            m1 = fmaxf(m1, r.y);
        }
        C00 = m0; C01 = m1;
        float w0 = __expf(a0 - m0);
        float w1 = __expf(a1 - m1);
        ((float*)(smem + SM_EA0))[tid] = w0;
        ((float*)(smem + SM_EA1))[tid] = w1;
        if (tid == 0) mslotF[0] = make_float2(w0, w1);
        __syncthreads();
    }

    const uint32_t ea0base = smem_base + SM_EA0 + jh * 512;
    const uint32_t ea1base = smem_base + SM_EA1 + jh * 512;
    const uint32_t partA   = smem_base + SM_PART + p * 32;
    const float* in0 = inputs + (size_t)b0 * TT * NS + 2 * p;
    const float* in1 = inputs + (size_t)b1 * TT * NS + 2 * p;

    int ksum0 = 0, ksum1 = 0;
    uint32_t cur = 0;  // byte offset of current ea buffer (0 / 1024)

    // preload emissions for t=1 (jh0 threads own phase D)
    float2 em0c = make_float2(0.f, 0.f), em1c = make_float2(0.f, 0.f);
    if (jh == 0) {
        em0c = *(const float2*)(in0 + (size_t)1 * NS);
        em1c = *(const float2*)(in1 + (size_t)1 * NS);
    }

    for (int t = 1; t < TT; t++) {
        // renorm factor from stale state-0 slot; fold into esw
        float2 ms = mslotF[cur >> 10];
        uint32_t e0b = (__float_as_uint(ms.x) >> 23) & 0xFFu;
        uint32_t e1b = (__float_as_uint(ms.y) >> 23) & 0xFFu;
        ksum0 += (int)e0b - 127;
        ksum1 += (int)e1b - 127;
        float invM0 = __uint_as_float((254u - e0b) << 23);
        float invM1 = __uint_as_float((254u - e1b) << 23);
        uint32_t mw = masksS[t - 1];

        float esw00, esw10, esw01, esw11;
        float2 em0n = make_float2(0.f, 0.f), em1n = make_float2(0.f, 0.f);
        if (jh == 0) {
            esw00 = __expf(em0c.x) * invM0;
            esw10 = __expf(em0c.y) * invM0;
            esw01 = __expf(em1c.x) * invM1;
            esw11 = __expf(em1c.y) * invM1;
            if (t + 1 < TT) {
                em0n = *(const float2*)(in0 + (size_t)(t + 1) * NS);
                em1n = *(const float2*)(in1 + (size_t)(t + 1) * NS);
            }
        }

        const uint32_t ea0 = ea0base + cur;
        const uint32_t ea1 = ea1base + cur;

        // ---- dot over this thread's 128-j range ----
        unsigned long long acc00 = 0ull, acc01 = 0ull, acc10 = 0ull, acc11 = 0ull;
#pragma unroll
        for (int k = 0; k < 16; k++) {
            unsigned long long la0, lb0, la1, lb1;   // lower-half ea (j 4k..4k+3)
            LDSV2(la0, lb0, ea0 + 16 * k);
            LDSV2(la1, lb1, ea1 + 16 * k);
            unsigned long long ha0, hb0, ha1, hb1;   // upper-half ea (j 64+4k..67+4k)
            LDSV2(ha0, hb0, ea0 + 256 + 16 * k);
            LDSV2(ha1, hb1, ea1 + 256 + 16 * k);

            // f32-register half
            FMA2(acc00, Er[4 * k + 0], la0);
            FMA2(acc01, Er[4 * k + 0], la1);
            FMA2(acc10, Er[4 * k + 1], la0);
            FMA2(acc11, Er[4 * k + 1], la1);
            FMA2(acc00, Er[4 * k + 2], lb0);
            FMA2(acc01, Er[4 * k + 2], lb1);
            FMA2(acc10, Er[4 * k + 3], lb0);
            FMA2(acc11, Er[4 * k + 3], lb1);

            // upper half: bf16 registers (k<8) or bf16 smem (k>=8)
            unsigned long long e0p, e1p, e0q, e1q;
            if (k < 8) {
                e0p = bf2f2(Ebr[4 * k + 0]);
                e1p = bf2f2(Ebr[4 * k + 1]);
                e0q = bf2f2(Ebr[4 * k + 2]);
                e1q = bf2f2(Ebr[4 * k + 3]);
            } else {
                uint4 ev = EsmS[(k - 8) * 256 + tid];
                e0p = bf2f2(ev.x);
                e1p = bf2f2(ev.y);
                e0q = bf2f2(ev.z);
                e1q = bf2f2(ev.w);
            }
            FMA2(acc00, e0p, ha0);
            FMA2(acc01, e0p, ha1);
            FMA2(acc10, e1p, ha0);
            FMA2(acc11, e1p, ha1);
            FMA2(acc00, e0q, hb0);
            FMA2(acc01, e0q, hb1);
            FMA2(acc10, e1q, hb0);
            FMA2(acc11, e1q, hb1);
        }
        if (jh) {
            STSV2(partA, acc00, acc01);
            STSV2(partA + 16, acc10, acc11);
        }
        __syncthreads();

        // rare masked path: need plain sums of current ea
        float S0 = 0.f, S1 = 0.f;
        if (mw != 3u) {
            float v0 = ((float*)(smem + SM_EA0 + cur))[tid];
            float v1 = ((float*)(smem + SM_EA1 + cur))[tid];
#pragma unroll
            for (int o = 16; o; o >>= 1) {
                v0 += __shfl_xor_sync(0xffffffffu, v0, o);
                v1 += __shfl_xor_sync(0xffffffffu, v1, o);
            }
            if (lane == 0) redF[wid] = make_float2(v0, v1);
            __syncthreads();
#pragma unroll
            for (int w = 0; w < 8; w++) {
                float2 r = redF[w];
                S0 += r.x;
                S1 += r.y;
            }
        }

        // ---- phase D: combine halves, scale, write next ea ----
        const uint32_t nxt = cur ^ 1024u;
        if (jh == 0) {
            unsigned long long qa, qb, qc, qd;
            LDSV2(qa, qb, partA);
            LDSV2(qc, qd, partA + 16);
            ADD2(acc00, qa);
            ADD2(acc01, qb);
            ADD2(acc10, qc);
            ADD2(acc11, qd);
            float u00 = f2sum(acc00) * esw00;
            float u01 = f2sum(acc01) * esw01;
            float u10 = f2sum(acc10) * esw10;
            float u11 = f2sum(acc11) * esw11;
            if (!(mw & 1u)) { float l = S0 * invM0; u00 = l; u10 = l; }
            if (!(mw & 2u)) { float l = S1 * invM1; u01 = l; u11 = l; }
            ((float2*)(smem + SM_EA0 + nxt))[p] = make_float2(u00, u10);
            ((float2*)(smem + SM_EA1 + nxt))[p] = make_float2(u01, u11);
            if (p == 0) mslotF[nxt >> 10] = make_float2(u00, u01);
        }
        em0c = em0n; em1c = em1n;
        cur = nxt;
        __syncthreads();
    }

    // epilogue: den[b] = C0 + ksum*ln2 + log(sum_s ea[s] * exp(trans[STOP,s]))
    {
        float ets = __expf(trans[STOP_TAG * NS + tid]);
        float v0 = ((float*)(smem + SM_EA0 + cur))[tid] * ets;
        float v1 = ((float*)(smem + SM_EA1 + cur))[tid] * ets;
#pragma unroll
        for (int o = 16; o; o >>= 1) {
            v0 += __shfl_xor_sync(0xffffffffu, v0, o);
            v1 += __shfl_xor_sync(0xffffffffu, v1, o);
        }
        if (lane == 0) redF[wid] = make_float2(v0, v1);
        __syncthreads();
        if (tid == 0) {
            float s0 = 0.f, s1 = 0.f;
#pragma unroll
            for (int w = 0; w < 8; w++) { s0 += redF[w].x; s1 += redF[w].y; }
            g_den[b0] = C00 + (float)ksum0 * LN2F + __logf(s0);
            g_den[b1] = C01 + (float)ksum1 * LN2F + __logf(s1);
        }
    }
}

// ---------------------------------------------------------------------------
// Numerator: 1 warp per batch
// ---------------------------------------------------------------------------
__global__ void num_kernel(const float* __restrict__ inputs,
                           const float* __restrict__ trans,
                           const int* __restrict__ tags,
                           const int* __restrict__ mask)
{
    int b = blockIdx.x;
    int lane = threadIdx.x;
    const int* tg = tags + b * TT;
    const int* mk = mask + b * TT;
    float sc = 0.f;
    int mc = 0;
    for (int t = lane; t < TT; t += 32) {
        int tgt = tg[t];
        int m = mk[t];
        mc += m;
        if (t >= 1) sc += trans[tgt * NS + tg[t - 1]] * (float)m;
        if (t < TT - 1) sc += inputs[((size_t)b * TT + t) * NS + tgt] * (float)m;
    }
#pragma unroll
    for (int o = 16; o; o >>= 1) {
        sc += __shfl_xor_sync(0xffffffffu, sc, o);
        mc += __shfl_xor_sync(0xffffffffu, mc, o);
    }
    if (lane == 0) {
        sc += trans[tg[0] * NS + START_TAG];
        int li = mc - 1;
        if (li < 0) li = 0;
        int lt = tg[li];
        sc += trans[STOP_TAG * NS + lt]
            + inputs[((size_t)b * TT + (TT - 1)) * NS + lt] * (float)mk[TT - 1];
        g_num[b] = sc;
    }
}

// ---------------------------------------------------------------------------
// Final reduce: sum_b (num - den)
// ---------------------------------------------------------------------------
__global__ void final_kernel(float* __restrict__ out)
{
    __shared__ float red[8];
    int tid = threadIdx.x;
    int lane = tid & 31, wid = tid >> 5;
    float v = g_num[tid] - g_den[tid];
#pragma unroll
    for (int o = 16; o; o >>= 1) v += __shfl_xor_sync(0xffffffffu, v, o);
    if (lane == 0) red[wid] = v;
    __syncthreads();
    if (tid == 0) {
        float s = 0.f;
#pragma unroll
        for (int w = 0; w < 8; w++) s += red[w];
        out[0] = s;
    }
}

extern "C" void kernel_launch(void* const* d_in, const int* in_sizes, int n_in,
                              void* d_out, int out_size)
{
    const float* inputs = (const float*)d_in[0];
    const float* trans  = (const float*)d_in[1];
    const int*   tags   = (const int*)d_in[2];
    const int*   mask   = (const int*)d_in[3];

    prep_kernel<<<256, 256>>>(trans);
    forward_kernel<<<BB / 2, 256, SM_TOTAL>>>(inputs, trans, mask);
    num_kernel<<<BB, 32>>>(inputs, trans, tags, mask);
    final_kernel<<<1, 256>>>((float*)d_out);
}

// round 6
// speedup vs baseline: 2.7201x; 1.5487x over previous
#include <cuda_runtime.h>
#include <cuda_bf16.h>
#include <cstdint>

#define BB 256
#define TT 512
#define NS 256
#define START_TAG 254
#define STOP_TAG 255
#define LN2F 0.6931471805599453f
#define NB 8
#define NCTA (BB / NB)
#define RSB 528           // ea row stride bytes (132 words -> conflict-free B loads)
#define EABUF (NB * RSB)  // 4224

// scratch (allocation-free rule: __device__ globals)
__device__ float g_den[BB];
__device__ float g_num[BB];
__device__ unsigned short g_Ebf[NS * NS];  // E = exp(trans), bf16 row-major

// ---------------------------------------------------------------------------
// smem layout (static, ~10.7 KB)
// ---------------------------------------------------------------------------
#define SM_EA    0        // 2 x 4224 ea double buffer: [n][j] bf16, stride RSB
#define SM_MSLOT 8448     // 2 x 8 floats (state-0 value per batch, renorm probe)
#define SM_MASK  8512     // 512 u32 mask bitfields
#define SM_C0    10560    // 8 floats
#define SM_RED   10592    // 64 floats
#define SM_KS    10848    // 8 ints
#define SM_SS    10880    // 8 floats
#define SM_TOTAL 10912

#define MMA_BF16(d, a, b0, b1) \
    asm volatile( \
        "mma.sync.aligned.m16n8k16.row.col.f32.bf16.bf16.f32 " \
        "{%0,%1,%2,%3},{%4,%5,%6,%7},{%8,%9},{%0,%1,%2,%3};" \
        : "+f"((d)[0]), "+f"((d)[1]), "+f"((d)[2]), "+f"((d)[3]) \
        : "r"((a)[0]), "r"((a)[1]), "r"((a)[2]), "r"((a)[3]), "r"(b0), "r"(b1))

// ---------------------------------------------------------------------------
// Prep: E[i][j] = bf16(exp(trans[i][j])), row-major
// ---------------------------------------------------------------------------
__global__ void prep_kernel(const float* __restrict__ trans) {
    int gid = blockIdx.x * blockDim.x + threadIdx.x;  // 0..65535
    g_Ebf[gid] = __bfloat16_as_ushort(__float2bfloat16(__expf(trans[gid])));
}

// ---------------------------------------------------------------------------
// Forward recursion via mma.sync bf16: D[256 states, 8 batches] per step.
// Linear space with stale state-0 power-of-2 renorm (exact via ksum).
// ---------------------------------------------------------------------------
__global__ void __launch_bounds__(256, 1) forward_kernel(
    const float* __restrict__ inputs,
    const float* __restrict__ trans,
    const int* __restrict__ mask)
{
    __shared__ __align__(16) char smem[SM_TOTAL];
    const uint32_t smem_base = (uint32_t)__cvta_generic_to_shared(smem);
    float*    mslotF = (float*)(smem + SM_MSLOT);
    uint32_t* masksS = (uint32_t*)(smem + SM_MASK);
    float*    C0sm   = (float*)(smem + SM_C0);
    float*    redsm  = (float*)(smem + SM_RED);
    int*      kssm   = (int*)(smem + SM_KS);
    float*    Ssm    = (float*)(smem + SM_SS);

    const int tid  = threadIdx.x;
    const int lane = tid & 31;
    const int wid  = tid >> 5;
    const int gidr = lane >> 2;   // groupID
    const int tig  = lane & 3;    // thread-in-group
    const int wbase = wid * 32;   // this warp's state base (2 m16 tiles)
    const int bb    = blockIdx.x * NB;
    const int n0 = 2 * tig, n1 = n0 + 1;  // this thread's two batch columns

    // mask bitfields
    for (int tt = tid; tt < TT; tt += 256) {
        uint32_t w = 0;
#pragma unroll
        for (int n = 0; n < NB; n++) w |= (mask[(bb + n) * TT + tt] ? 1u : 0u) << n;
        masksS[tt] = w;
    }

    // A fragments: whole E in registers (128 u32/thread)
    uint32_t A[2][16][4];
    {
#pragma unroll
        for (int mt = 0; mt < 2; mt++) {
            int r0 = wbase + mt * 16 + gidr, r1 = r0 + 8;
#pragma unroll
            for (int kt = 0; kt < 16; kt++) {
                int c0 = kt * 16 + tig * 2;
                A[mt][kt][0] = *(const uint32_t*)&g_Ebf[r0 * NS + c0];
                A[mt][kt][1] = *(const uint32_t*)&g_Ebf[r1 * NS + c0];
                A[mt][kt][2] = *(const uint32_t*)&g_Ebf[r0 * NS + c0 + 8];
                A[mt][kt][3] = *(const uint32_t*)&g_Ebf[r1 * NS + c0 + 8];
            }
        }
    }

    // alpha0: per-batch max -> C0; ea0 = bf16(exp(alpha0 - C0))
    {
        float a0v[NB];
        float tS = trans[tid * NS + START_TAG];
#pragma unroll
        for (int n = 0; n < NB; n++)
            a0v[n] = tS + inputs[((size_t)(bb + n) * TT) * NS + tid];
#pragma unroll
        for (int n = 0; n < NB; n++) {
            float m = a0v[n];
#pragma unroll
            for (int o = 16; o; o >>= 1) m = fmaxf(m, __shfl_xor_sync(~0u, m, o));
            if (lane == 0) redsm[wid * 8 + n] = m;
        }
        __syncthreads();
        if (tid < 8) {
            float m = -INFINITY;
#pragma unroll
            for (int w = 0; w < 8; w++) m = fmaxf(m, redsm[w * 8 + tid]);
            C0sm[tid] = m;
        }
        __syncthreads();
#pragma unroll
        for (int n = 0; n < NB; n++) {
            float e = __expf(a0v[n] - C0sm[n]);
            unsigned short h = __bfloat16_as_ushort(__float2bfloat16(e));
            uint32_t ad = smem_base + SM_EA + (uint32_t)(n * RSB + tid * 2);
            asm volatile("st.shared.b16 [%0], %1;" :: "r"(ad), "h"(h));
            if (tid == 0) mslotF[n] = e;
        }
        __syncthreads();
    }

    // emission prefetch pointers (this thread's 4 states x 2 batches)
    const float* pn0 = inputs + (size_t)(bb + n0) * TT * NS;
    const float* pn1 = inputs + (size_t)(bb + n1) * TT * NS;
    const int m00 = wbase + gidr, m01 = m00 + 8, m10 = m00 + 16, m11 = m00 + 24;

    float emA[8], emB[8];
    {
        const float* q0 = pn0 + (size_t)1 * NS;
        const float* q1 = pn1 + (size_t)1 * NS;
        emA[0] = q0[m00]; emA[1] = q1[m00]; emA[2] = q0[m01]; emA[3] = q1[m01];
        emA[4] = q0[m10]; emA[5] = q1[m10]; emA[6] = q0[m11]; emA[7] = q1[m11];
    }
    {
        const float* q0 = pn0 + (size_t)2 * NS;
        const float* q1 = pn1 + (size_t)2 * NS;
        emB[0] = q0[m00]; emB[1] = q1[m00]; emB[2] = q0[m01]; emB[3] = q1[m01];
        emB[4] = q0[m10]; emB[5] = q1[m10]; emB[6] = q0[m11]; emB[7] = q1[m11];
    }

    int ksum0 = 0, ksum1 = 0;
    uint32_t cur = 0;

    for (int t = 1; t < TT; t++) {
        const uint32_t bufb = smem_base + SM_EA + cur * EABUF;
        float d0[4] = {0.f, 0.f, 0.f, 0.f};
        float d1[4] = {0.f, 0.f, 0.f, 0.f};
#pragma unroll
        for (int kt = 0; kt < 16; kt++) {
            uint32_t b0, b1;
            uint32_t ad = bufb + (uint32_t)(gidr * RSB + kt * 32 + tig * 4);
            asm volatile("ld.shared.b32 %0,[%1];" : "=r"(b0) : "r"(ad));
            asm volatile("ld.shared.b32 %0,[%1];" : "=r"(b1) : "r"(ad + 16));
            MMA_BF16(d0, A[0][kt], b0, b1);
            MMA_BF16(d1, A[1][kt], b0, b1);
        }

        // stale renorm from state-0 slots (exact power of 2, tracked in ksum)
        float ms0 = mslotF[cur * 8 + n0];
        float ms1 = mslotF[cur * 8 + n1];
        uint32_t e0b = (__float_as_uint(ms0) >> 23) & 0xFFu;
        uint32_t e1b = (__float_as_uint(ms1) >> 23) & 0xFFu;
        ksum0 += (int)e0b - 127;
        ksum1 += (int)e1b - 127;
        float invM0 = __uint_as_float((254u - e0b) << 23);
        float invM1 = __uint_as_float((254u - e1b) << 23);
        uint32_t mw = masksS[t - 1];

        float es[8];
#pragma unroll
        for (int i = 0; i < 8; i += 2) {
            es[i]     = __expf(emA[i]) * invM0;
            es[i + 1] = __expf(emA[i + 1]) * invM1;
        }
        // rotate prefetch (2 steps deep)
#pragma unroll
        for (int i = 0; i < 8; i++) emA[i] = emB[i];
        if (t + 2 < TT) {
            const float* q0 = pn0 + (size_t)(t + 2) * NS;
            const float* q1 = pn1 + (size_t)(t + 2) * NS;
            emB[0] = q0[m00]; emB[1] = q1[m00]; emB[2] = q0[m01]; emB[3] = q1[m01];
            emB[4] = q0[m10]; emB[5] = q1[m10]; emB[6] = q0[m11]; emB[7] = q1[m11];
        }

        // rare masked path: need per-batch sums of current ea
        float Sv0 = 0.f, Sv1 = 0.f;
        if (mw != 0xFFu) {
            if (wid < 8) {
                float s = 0.f;
#pragma unroll
                for (int q = 0; q < 4; q++) {
                    uint32_t v;
                    uint32_t ad = bufb + (uint32_t)(wid * RSB + (lane * 4 + q) * 4);
                    asm volatile("ld.shared.b32 %0,[%1];" : "=r"(v) : "r"(ad));
                    s += __uint_as_float(v << 16) + __uint_as_float(v & 0xFFFF0000u);
                }
#pragma unroll
                for (int o = 16; o; o >>= 1) s += __shfl_xor_sync(~0u, s, o);
                if (lane == 0) Ssm[wid] = s;
            }
            __syncthreads();
            Sv0 = Ssm[n0] * invM0;
            Sv1 = Ssm[n1] * invM1;
        }

        // epilogue: u = d * exp(em) * invM, write bf16 to next buffer
        const uint32_t nxtb = smem_base + SM_EA + (cur ^ 1u) * EABUF;
        float u00 = d0[0] * es[0], u01 = d0[1] * es[1];
        float u02 = d0[2] * es[2], u03 = d0[3] * es[3];
        float u10 = d1[0] * es[4], u11 = d1[1] * es[5];
        float u12 = d1[2] * es[6], u13 = d1[3] * es[7];
        if (mw != 0xFFu) {
            if (!((mw >> n0) & 1u)) { u00 = Sv0; u02 = Sv0; u10 = Sv0; u12 = Sv0; }
            if (!((mw >> n1) & 1u)) { u01 = Sv1; u03 = Sv1; u11 = Sv1; u13 = Sv1; }
        }
        {
            uint32_t a0 = nxtb + (uint32_t)(n0 * RSB);
            uint32_t a1 = nxtb + (uint32_t)(n1 * RSB);
            unsigned short h;
#define STB(addr, val) \
            h = __bfloat16_as_ushort(__float2bfloat16(val)); \
            asm volatile("st.shared.b16 [%0], %1;" :: "r"(addr), "h"(h))
            STB(a0 + m00 * 2, u00); STB(a1 + m00 * 2, u01);
            STB(a0 + m01 * 2, u02); STB(a1 + m01 * 2, u03);
            STB(a0 + m10 * 2, u10); STB(a1 + m10 * 2, u11);
            STB(a0 + m11 * 2, u12); STB(a1 + m11 * 2, u13);
#undef STB
        }
        if (tid < 4) {  // warp0 lanes 0..3 hold state 0 (gidr==0, m00==0)
            mslotF[(cur ^ 1u) * 8 + n0] = u00;
            mslotF[(cur ^ 1u) * 8 + n1] = u01;
        }
        __syncthreads();
        cur ^= 1u;
    }

    // epilogue: den[b] = C0 + ksum*ln2 + log(sum_j ea[j][b] * exp(trans[STOP,j]))
    {
        float ets = __expf(trans[STOP_TAG * NS + tid]);
        const uint32_t bufb = smem_base + SM_EA + cur * EABUF;
        float v[NB];
#pragma unroll
        for (int n = 0; n < NB; n++) {
            uint32_t hv;
            uint32_t ad = bufb + (uint32_t)(n * RSB + tid * 2);
            asm volatile("ld.shared.u16 %0,[%1];" : "=r"(hv) : "r"(ad));
            v[n] = __uint_as_float(hv << 16) * ets;
        }
#pragma unroll
        for (int n = 0; n < NB; n++) {
            float s = v[n];
#pragma unroll
            for (int o = 16; o; o >>= 1) s += __shfl_xor_sync(~0u, s, o);
            if (lane == 0) redsm[wid * 8 + n] = s;
        }
        if (tid < 4) { kssm[n0] = ksum0; kssm[n1] = ksum1; }
        __syncthreads();
        if (tid < 8) {
            float s = 0.f;
#pragma unroll
            for (int w = 0; w < 8; w++) s += redsm[w * 8 + tid];
            g_den[bb + tid] = C0sm[tid] + (float)kssm[tid] * LN2F + __logf(s);
        }
    }
}

// ---------------------------------------------------------------------------
// Numerator: 1 warp per batch
// ---------------------------------------------------------------------------
__global__ void num_kernel(const float* __restrict__ inputs,
                           const float* __restrict__ trans,
                           const int* __restrict__ tags,
                           const int* __restrict__ mask)
{
    int b = blockIdx.x;
    int lane = threadIdx.x;
    const int* tg = tags + b * TT;
    const int* mk = mask + b * TT;
    float sc = 0.f;
    int mc = 0;
    for (int t = lane; t < TT; t += 32) {
        int tgt = tg[t];
        int m = mk[t];
        mc += m;
        if (t >= 1) sc += trans[tgt * NS + tg[t - 1]] * (float)m;
        if (t < TT - 1) sc += inputs[((size_t)b * TT + t) * NS + tgt] * (float)m;
    }
#pragma unroll
    for (int o = 16; o; o >>= 1) {
        sc += __shfl_xor_sync(0xffffffffu, sc, o);
        mc += __shfl_xor_sync(0xffffffffu, mc, o);
    }
    if (lane == 0) {
        sc += trans[tg[0] * NS + START_TAG];
        int li = mc - 1;
        if (li < 0) li = 0;
        int lt = tg[li];
        sc += trans[STOP_TAG * NS + lt]
            + inputs[((size_t)b * TT + (TT - 1)) * NS + lt] * (float)mk[TT - 1];
        g_num[b] = sc;
    }
}

// ---------------------------------------------------------------------------
// Final reduce: sum_b (num - den)
// ---------------------------------------------------------------------------
__global__ void final_kernel(float* __restrict__ out)
{
    __shared__ float red[8];
    int tid = threadIdx.x;
    int lane = tid & 31, wid = tid >> 5;
    float v = g_num[tid] - g_den[tid];
#pragma unroll
    for (int o = 16; o; o >>= 1) v += __shfl_xor_sync(0xffffffffu, v, o);
    if (lane == 0) red[wid] = v;
    __syncthreads();
    if (tid == 0) {
        float s = 0.f;
#pragma unroll
        for (int w = 0; w < 8; w++) s += red[w];
        out[0] = s;
    }
}

extern "C" void kernel_launch(void* const* d_in, const int* in_sizes, int n_in,
                              void* d_out, int out_size)
{
    const float* inputs = (const float*)d_in[0];
    const float* trans  = (const float*)d_in[1];
    const int*   tags   = (const int*)d_in[2];
    const int*   mask   = (const int*)d_in[3];

    prep_kernel<<<256, 256>>>(trans);
    forward_kernel<<<NCTA, 256>>>(inputs, trans, mask);
    num_kernel<<<BB, 32>>>(inputs, trans, tags, mask);
    final_kernel<<<1, 256>>>((float*)d_out);
}